// round 5
// baseline (speedup 1.0000x reference)
#include <cuda_runtime.h>
#include <cuda_bf16.h>
#include <stdint.h>

// ---------------- problem sizes ----------------
#define BATCH 4096
#define OBSD  256
#define HID   2048
#define OUTD  16384   // FEAT*ACT
#define ADIM  32
#define FDIM  512

// ---------------- scratch (device globals) ----------
#define TRUNK_W 42467328
__device__ __align__(1024) __nv_bfloat16 g_wt_hi[2 * TRUNK_W];
__device__ __align__(1024) __nv_bfloat16 g_wt_lo[2 * TRUNK_W];
__device__ __align__(1024) __nv_bfloat16 g_act_hi[2][BATCH * HID];
__device__ __align__(1024) __nv_bfloat16 g_act_lo[2][BATCH * HID];
__device__ __align__(1024) float         g_tout[2][BATCH * OUTD];

// ---------------- helpers ----------------
static __device__ __forceinline__ uint32_t smem_u32(const void* p) {
    uint32_t a;
    asm volatile("{ .reg .u64 t; cvta.to.shared.u64 t, %1; cvt.u32.u64 %0, t; }"
                 : "=r"(a) : "l"(p));
    return a;
}
static __device__ __forceinline__ void cp16(uint32_t dst, const void* src) {
    asm volatile("cp.async.cg.shared.global [%0], [%1], 16;" :: "r"(dst), "l"(src));
}
static __device__ __forceinline__ void cp_commit() { asm volatile("cp.async.commit_group;"); }
template <int N> static __device__ __forceinline__ void cp_wait() {
    asm volatile("cp.async.wait_group %0;" :: "n"(N) : "memory");
}
static __device__ __forceinline__ void ldsm4(uint32_t (&d)[4], uint32_t addr) {
    asm volatile("ldmatrix.sync.aligned.m8n8.x4.shared.b16 {%0,%1,%2,%3}, [%4];"
                 : "=r"(d[0]), "=r"(d[1]), "=r"(d[2]), "=r"(d[3]) : "r"(addr));
}
static __device__ __forceinline__ void mma16816(float (&c)[4], const uint32_t a0,
                                                const uint32_t a1, const uint32_t a2,
                                                const uint32_t a3, const uint32_t b0,
                                                const uint32_t b1) {
    asm volatile("mma.sync.aligned.m16n8k16.row.col.f32.bf16.bf16.f32 "
                 "{%0,%1,%2,%3}, {%4,%5,%6,%7}, {%8,%9}, {%0,%1,%2,%3};"
                 : "+f"(c[0]), "+f"(c[1]), "+f"(c[2]), "+f"(c[3])
                 : "r"(a0), "r"(a1), "r"(a2), "r"(a3), "r"(b0), "r"(b1));
}
static __device__ __forceinline__ uint32_t pack_bf16(float x, float y) {
    uint32_t r;
    asm("cvt.rn.bf16x2.f32 %0, %1, %2;" : "=r"(r) : "f"(y), "f"(x));
    return r;
}

// ---------------- GEMM (mma.sync, hi/lo 3-pass) -------------------
// C[M, Ntot] = A[M,K] @ B^T (+bias; ReLU+resplit unless LAST)
// Tile 128x128x32, 8 warps (2x4), warp tile 64x32.
#define BM 128
#define BN 128
#define BK 32
#define STR_H 40                      // halfs per smem row (32 data + 8 pad)
#define ARR_B (BM * STR_H * 2)        // bytes per array per stage = 10240
#define S_AH 0
#define S_AL ARR_B
#define S_BH (2 * ARR_B)
#define S_BL (3 * ARR_B)
#define STAGE_BYTES (4 * ARR_B)       // 40960
#define NSTAGE 3
#define GEMM_SMEM (NSTAGE * STAGE_BYTES)  // 122880

struct TileSrc {
    const __nv_bfloat16 *Ah, *Al, *Bh, *Bl;
    int K, tid;
};

static __device__ __forceinline__ void load_stage(uint32_t so, const TileSrc& ts, int kc) {
    const int k0 = kc * BK;
#pragma unroll
    for (int i = 0; i < 2; i++) {
        const int idx = ts.tid + i * 256;      // 0..511
        const int r = idx >> 2, q = idx & 3;
        const uint32_t o = (uint32_t)(r * (STR_H * 2) + q * 16);
        const size_t g = (size_t)r * ts.K + k0 + q * 8;
        cp16(so + S_AH + o, ts.Ah + g);
        cp16(so + S_AL + o, ts.Al + g);
        cp16(so + S_BH + o, ts.Bh + g);
        cp16(so + S_BL + o, ts.Bl + g);
    }
    cp_commit();
}

template <bool LAST>
__global__ void __launch_bounds__(256, 1)
gemm_kernel(const __nv_bfloat16* __restrict__ Ah, const __nv_bfloat16* __restrict__ Al,
            const __nv_bfloat16* __restrict__ Bh, const __nv_bfloat16* __restrict__ Bl,
            const float* __restrict__ bias,
            __nv_bfloat16* __restrict__ Ch, __nv_bfloat16* __restrict__ Cl,
            float* __restrict__ Cf,
            int K, int Ntot)
{
    extern __shared__ char dsm[];
    const uint32_t sb = smem_u32(dsm);
    const int tid = threadIdx.x, wid = tid >> 5, lane = tid & 31;
    const int wm = wid >> 2, wn = wid & 3;          // 2 x 4 warp grid
    const int m0 = blockIdx.x * BM, n0 = blockIdx.y * BN;

    TileSrc ts;
    ts.Ah = Ah + (size_t)m0 * K;
    ts.Al = Al + (size_t)m0 * K;
    ts.Bh = Bh + (size_t)n0 * K;
    ts.Bl = Bl + (size_t)n0 * K;
    ts.K = K; ts.tid = tid;

    const int NK = K / BK;

    load_stage(sb + 0 * STAGE_BYTES, ts, 0);
    load_stage(sb + 1 * STAGE_BYTES, ts, 1);

    float acc[16][4] = {};

    // ldmatrix per-lane base: row (lane&15), col-half (lane>>4)*8
    const uint32_t frag_off = (uint32_t)((lane & 15) * STR_H + (lane >> 4) * 8) * 2;
    const uint32_t a_warp = (uint32_t)(wm * 64) * (STR_H * 2);
    const uint32_t b_warp = (uint32_t)(wn * 32) * (STR_H * 2);

#pragma unroll 1
    for (int kc = 0; kc < NK; kc++) {
        if (kc + 2 < NK) {
            load_stage(sb + ((kc + 2) % NSTAGE) * STAGE_BYTES, ts, kc + 2);
            cp_wait<2>();
        } else {
            cp_wait<0>();
        }
        __syncthreads();
        const uint32_t so = sb + (kc % NSTAGE) * STAGE_BYTES;
#pragma unroll
        for (int kk = 0; kk < 2; kk++) {        // two k16 steps per BK=32 chunk
            const uint32_t ko = (uint32_t)(kk * 16 * 2);
            uint32_t ah[4][4], al[4][4], bh[2][4], bl[2][4];
#pragma unroll
            for (int mt = 0; mt < 4; mt++) {
                const uint32_t ao = a_warp + (uint32_t)(mt * 16) * (STR_H * 2) + ko + frag_off;
                ldsm4(ah[mt], so + S_AH + ao);
                ldsm4(al[mt], so + S_AL + ao);
            }
#pragma unroll
            for (int t = 0; t < 2; t++) {
                const uint32_t bo = b_warp + (uint32_t)(t * 16) * (STR_H * 2) + ko + frag_off;
                ldsm4(bh[t], so + S_BH + bo);
                ldsm4(bl[t], so + S_BL + bo);
            }
#pragma unroll
            for (int mt = 0; mt < 4; mt++)
#pragma unroll
                for (int nt = 0; nt < 4; nt++) {
                    const int t = nt >> 1, od = nt & 1;
                    float (&c)[4] = acc[mt * 4 + nt];
                    mma16816(c, ah[mt][0], ah[mt][1], ah[mt][2], ah[mt][3],
                             bh[t][od], bh[t][od + 2]);
                    mma16816(c, ah[mt][0], ah[mt][1], ah[mt][2], ah[mt][3],
                             bl[t][od], bl[t][od + 2]);
                    mma16816(c, al[mt][0], al[mt][1], al[mt][2], al[mt][3],
                             bh[t][od], bh[t][od + 2]);
                }
        }
        __syncthreads();
    }

    // -------- epilogue: bias (+ReLU + hi/lo resplit) straight from registers
    const int er = lane >> 2, ec = (lane & 3) * 2;
#pragma unroll
    for (int mt = 0; mt < 4; mt++) {
#pragma unroll
        for (int nt = 0; nt < 4; nt++) {
            const int col = n0 + wn * 32 + nt * 8 + ec;
            const int r0 = m0 + wm * 64 + mt * 16 + er;
            const float2 bv = *reinterpret_cast<const float2*>(bias + col);
            float v0 = acc[mt * 4 + nt][0] + bv.x;
            float v1 = acc[mt * 4 + nt][1] + bv.y;
            float v2 = acc[mt * 4 + nt][2] + bv.x;
            float v3 = acc[mt * 4 + nt][3] + bv.y;
            if (LAST) {
                *reinterpret_cast<float2*>(Cf + (size_t)r0 * Ntot + col)       = make_float2(v0, v1);
                *reinterpret_cast<float2*>(Cf + (size_t)(r0 + 8) * Ntot + col) = make_float2(v2, v3);
            } else {
                v0 = fmaxf(v0, 0.f); v1 = fmaxf(v1, 0.f);
                v2 = fmaxf(v2, 0.f); v3 = fmaxf(v3, 0.f);
                float h0 = __bfloat162float(__float2bfloat16(v0));
                float h1 = __bfloat162float(__float2bfloat16(v1));
                float h2 = __bfloat162float(__float2bfloat16(v2));
                float h3 = __bfloat162float(__float2bfloat16(v3));
                *reinterpret_cast<uint32_t*>(Ch + (size_t)r0 * Ntot + col)       = pack_bf16(h0, h1);
                *reinterpret_cast<uint32_t*>(Ch + (size_t)(r0 + 8) * Ntot + col) = pack_bf16(h2, h3);
                *reinterpret_cast<uint32_t*>(Cl + (size_t)r0 * Ntot + col)       = pack_bf16(v0 - h0, v1 - h1);
                *reinterpret_cast<uint32_t*>(Cl + (size_t)(r0 + 8) * Ntot + col) = pack_bf16(v2 - h2, v3 - h3);
            }
        }
    }
}

// ---------------- prep kernels -------------------
__global__ void __launch_bounds__(256) split_kernel(const float* __restrict__ x,
                                                    __nv_bfloat16* __restrict__ hi,
                                                    __nv_bfloat16* __restrict__ lo, int n) {
    int i = blockIdx.x * 256 + threadIdx.x;
    if (i < n) {
        float v = x[i];
        __nv_bfloat16 h = __float2bfloat16(v);
        hi[i] = h;
        lo[i] = __float2bfloat16(v - __bfloat162float(h));
    }
}

// W [din][dout] fp32 row-major -> Wt hi/lo [dout][din] bf16 row-major
__global__ void __launch_bounds__(256) transpose_split_kernel(
    const float* __restrict__ W, __nv_bfloat16* __restrict__ thi,
    __nv_bfloat16* __restrict__ tlo, int din, int dout) {
    __shared__ float t[32][33];
    const int tx = threadIdx.x, ty = threadIdx.y;
    const int n0 = blockIdx.x * 32, k0 = blockIdx.y * 32;
#pragma unroll
    for (int i = 0; i < 4; i++)
        t[ty + i * 8][tx] = W[(size_t)(k0 + ty + i * 8) * dout + n0 + tx];
    __syncthreads();
#pragma unroll
    for (int i = 0; i < 4; i++) {
        float v = t[tx][ty + i * 8];
        __nv_bfloat16 h = __float2bfloat16(v);
        size_t o = (size_t)(n0 + ty + i * 8) * din + k0 + tx;
        thi[o] = h;
        tlo[o] = __float2bfloat16(v - __bfloat162float(h));
    }
}

// ---------------- bilinear -----------------------
// out[b][a] = sum_f ob[b][a*512+f] * dl[b][f*32+a]
__global__ void __launch_bounds__(256) bilinear_kernel(const float* __restrict__ ob,
                                                       const float* __restrict__ dl,
                                                       float* __restrict__ out) {
    __shared__ float s_dl[64 * 33];
    const int b = blockIdx.x;
    const int tid = threadIdx.x, w = tid >> 5, lane = tid & 31;
    const float* obr = ob + (size_t)b * OUTD;
    const float* dlr = dl + (size_t)b * OUTD;
    float acc[4] = {0.f, 0.f, 0.f, 0.f};
#pragma unroll 1
    for (int f0 = 0; f0 < FDIM; f0 += 64) {
#pragma unroll
        for (int i = 0; i < 8; i++) {
            int t = tid + i * 256;
            s_dl[(t >> 5) * 33 + (t & 31)] = dlr[f0 * ADIM + t];
        }
        __syncthreads();
#pragma unroll
        for (int ai = 0; ai < 4; ai++) {
            const int a = w * 4 + ai;
            const float* po = obr + a * FDIM + f0;
#pragma unroll
            for (int h = 0; h < 2; h++) {
                int ff = h * 32 + lane;
                acc[ai] += po[ff] * s_dl[ff * 33 + a];
            }
        }
        __syncthreads();
    }
#pragma unroll
    for (int ai = 0; ai < 4; ai++) {
        float v = acc[ai];
#pragma unroll
        for (int off = 16; off; off >>= 1) v += __shfl_xor_sync(0xffffffffu, v, off);
        if (lane == 0) out[b * ADIM + w * 4 + ai] = v;
    }
}

// ---------------- host launcher -------------------
static const size_t LOFF[4] = {0, 524288, 4718592, 8912896};
static const int LDIN[4]  = {OBSD, HID, HID, HID};
static const int LDOUT[4] = {HID, HID, HID, OUTD};

extern "C" void kernel_launch(void* const* d_in, const int* in_sizes, int n_in,
                              void* d_out, int out_size) {
    (void)in_sizes; (void)n_in; (void)out_size;
    const float* obs = (const float*)d_in[0];
    const float* del = (const float*)d_in[1];
    const float* W[2][4];
    const float* Bv[2][4];
    for (int l = 0; l < 4; l++) {
        W[0][l]  = (const float*)d_in[2 + l * 4 + 0];
        Bv[0][l] = (const float*)d_in[2 + l * 4 + 1];
        W[1][l]  = (const float*)d_in[2 + l * 4 + 2];
        Bv[1][l] = (const float*)d_in[2 + l * 4 + 3];
    }

    __nv_bfloat16 *wth, *wtl, *ahb, *alb;
    float* tob;
    cudaGetSymbolAddress((void**)&wth, g_wt_hi);
    cudaGetSymbolAddress((void**)&wtl, g_wt_lo);
    cudaGetSymbolAddress((void**)&ahb, g_act_hi);
    cudaGetSymbolAddress((void**)&alb, g_act_lo);
    cudaGetSymbolAddress((void**)&tob, g_tout);
    __nv_bfloat16* AH[2] = {ahb, ahb + (size_t)BATCH * HID};
    __nv_bfloat16* AL[2] = {alb, alb + (size_t)BATCH * HID};
    float* TO[2] = {tob, tob + (size_t)BATCH * OUTD};

    cudaFuncSetAttribute(gemm_kernel<false>, cudaFuncAttributeMaxDynamicSharedMemorySize, GEMM_SMEM);
    cudaFuncSetAttribute(gemm_kernel<true>,  cudaFuncAttributeMaxDynamicSharedMemorySize, GEMM_SMEM);

    for (int t = 0; t < 2; t++)
        for (int l = 0; l < 4; l++) {
            dim3 g(LDOUT[l] / 32, LDIN[l] / 32), bl(32, 8);
            transpose_split_kernel<<<g, bl>>>(W[t][l],
                                              wth + (size_t)t * TRUNK_W + LOFF[l],
                                              wtl + (size_t)t * TRUNK_W + LOFF[l],
                                              LDIN[l], LDOUT[l]);
        }

    for (int t = 0; t < 2; t++) {
        const float* x = (t == 0) ? obs : del;
        split_kernel<<<(BATCH * OBSD) / 256, 256>>>(x, AH[0], AL[0], BATCH * OBSD);
        const __nv_bfloat16* wh = wth + (size_t)t * TRUNK_W;
        const __nv_bfloat16* wl = wtl + (size_t)t * TRUNK_W;
        gemm_kernel<false><<<dim3(32, HID / BN), 256, GEMM_SMEM>>>(
            AH[0], AL[0], wh + LOFF[0], wl + LOFF[0], Bv[t][0],
            AH[1], AL[1], nullptr, OBSD, HID);
        gemm_kernel<false><<<dim3(32, HID / BN), 256, GEMM_SMEM>>>(
            AH[1], AL[1], wh + LOFF[1], wl + LOFF[1], Bv[t][1],
            AH[0], AL[0], nullptr, HID, HID);
        gemm_kernel<false><<<dim3(32, HID / BN), 256, GEMM_SMEM>>>(
            AH[0], AL[0], wh + LOFF[2], wl + LOFF[2], Bv[t][2],
            AH[1], AL[1], nullptr, HID, HID);
        gemm_kernel<true><<<dim3(32, OUTD / BN), 256, GEMM_SMEM>>>(
            AH[1], AL[1], wh + LOFF[3], wl + LOFF[3], Bv[t][3],
            nullptr, nullptr, TO[t], HID, OUTD);
    }

    bilinear_kernel<<<BATCH, 256>>>(TO[0], TO[1], (float*)d_out);
}

// round 6
// speedup vs baseline: 1.0682x; 1.0682x over previous
#include <cuda_runtime.h>
#include <cuda_bf16.h>
#include <stdint.h>

// ---------------- problem sizes ----------------
#define BATCH 4096
#define OBSD  256
#define HID   2048
#define OUTD  16384   // FEAT*ACT
#define ADIM  32
#define FDIM  512

// ---------------- scratch (device globals) ----------
#define TRUNK_W 42467328
__device__ __align__(1024) __nv_bfloat16 g_wt_hi[2 * TRUNK_W];
__device__ __align__(1024) __nv_bfloat16 g_wt_lo[2 * TRUNK_W];
__device__ __align__(1024) __nv_bfloat16 g_act_hi[2][BATCH * HID];
__device__ __align__(1024) __nv_bfloat16 g_act_lo[2][BATCH * HID];
__device__ __align__(1024) float         g_tout[2][BATCH * OUTD];

// ---------------- helpers ----------------
static __device__ __forceinline__ uint32_t smem_u32(const void* p) {
    uint32_t a;
    asm volatile("{ .reg .u64 t; cvta.to.shared.u64 t, %1; cvt.u32.u64 %0, t; }"
                 : "=r"(a) : "l"(p));
    return a;
}
static __device__ __forceinline__ void cp16(uint32_t dst, const void* src) {
    asm volatile("cp.async.cg.shared.global [%0], [%1], 16;" :: "r"(dst), "l"(src));
}
static __device__ __forceinline__ void cp_commit() { asm volatile("cp.async.commit_group;"); }
template <int N> static __device__ __forceinline__ void cp_wait() {
    asm volatile("cp.async.wait_group %0;" :: "n"(N) : "memory");
}
static __device__ __forceinline__ void ldsm4(uint32_t (&d)[4], uint32_t addr) {
    asm volatile("ldmatrix.sync.aligned.m8n8.x4.shared.b16 {%0,%1,%2,%3}, [%4];"
                 : "=r"(d[0]), "=r"(d[1]), "=r"(d[2]), "=r"(d[3]) : "r"(addr));
}
static __device__ __forceinline__ void mma16816(float (&c)[4], const uint32_t a0,
                                                const uint32_t a1, const uint32_t a2,
                                                const uint32_t a3, const uint32_t b0,
                                                const uint32_t b1) {
    asm volatile("mma.sync.aligned.m16n8k16.row.col.f32.bf16.bf16.f32 "
                 "{%0,%1,%2,%3}, {%4,%5,%6,%7}, {%8,%9}, {%0,%1,%2,%3};"
                 : "+f"(c[0]), "+f"(c[1]), "+f"(c[2]), "+f"(c[3])
                 : "r"(a0), "r"(a1), "r"(a2), "r"(a3), "r"(b0), "r"(b1));
}
static __device__ __forceinline__ uint32_t pack_bf16(float x, float y) {
    uint32_t r;
    asm("cvt.rn.bf16x2.f32 %0, %1, %2;" : "=r"(r) : "f"(y), "f"(x));
    return r;
}

// ---------------- GEMM (mma.sync, hi/lo 3-pass) -------------------
// C[M, Ntot] = A[M,K] @ B^T (+bias; ReLU+resplit unless LAST)
// Block tile 128x256x32, 8 warps in 2x4 grid, warp tile 64x64.
#define BM 128
#define BN 256
#define BK 32
#define STR_H 40                        // halfs per smem row (32 data + 8 pad)
#define ROW_B (STR_H * 2)               // 80 bytes per row
#define A_BYTES (BM * ROW_B)            // 10240
#define B_BYTES (BN * ROW_B)            // 20480
#define S_AH 0
#define S_AL A_BYTES
#define S_BH (2 * A_BYTES)
#define S_BL (2 * A_BYTES + B_BYTES)
#define STAGE_BYTES (2 * A_BYTES + 2 * B_BYTES)   // 61440
#define NSTAGE 3
#define GEMM_SMEM (NSTAGE * STAGE_BYTES)          // 184320

struct TileSrc {
    const __nv_bfloat16 *Ah, *Al, *Bh, *Bl;
    int K, tid;
};

static __device__ __forceinline__ void load_stage(uint32_t so, const TileSrc& ts, int kc) {
    const int k0 = kc * BK;
    // A: 128 rows x 4 chunks = 512 quads per array
#pragma unroll
    for (int i = 0; i < 2; i++) {
        const int idx = ts.tid + i * 256;
        const int r = idx >> 2, q = idx & 3;
        const uint32_t o = (uint32_t)(r * ROW_B + q * 16);
        const size_t g = (size_t)r * ts.K + k0 + q * 8;
        cp16(so + S_AH + o, ts.Ah + g);
        cp16(so + S_AL + o, ts.Al + g);
    }
    // B: 256 rows x 4 chunks = 1024 quads per array
#pragma unroll
    for (int i = 0; i < 4; i++) {
        const int idx = ts.tid + i * 256;
        const int r = idx >> 2, q = idx & 3;
        const uint32_t o = (uint32_t)(r * ROW_B + q * 16);
        const size_t g = (size_t)r * ts.K + k0 + q * 8;
        cp16(so + S_BH + o, ts.Bh + g);
        cp16(so + S_BL + o, ts.Bl + g);
    }
    cp_commit();
}

template <bool LAST>
__global__ void __launch_bounds__(256, 1)
gemm_kernel(const __nv_bfloat16* __restrict__ Ah, const __nv_bfloat16* __restrict__ Al,
            const __nv_bfloat16* __restrict__ Bh, const __nv_bfloat16* __restrict__ Bl,
            const float* __restrict__ bias,
            __nv_bfloat16* __restrict__ Ch, __nv_bfloat16* __restrict__ Cl,
            float* __restrict__ Cf,
            int K, int Ntot)
{
    extern __shared__ char dsm[];
    const uint32_t sb = smem_u32(dsm);
    const int tid = threadIdx.x, wid = tid >> 5, lane = tid & 31;
    const int wm = wid >> 2, wn = wid & 3;          // 2 x 4 warp grid
    const int m0 = blockIdx.x * BM, n0 = blockIdx.y * BN;

    TileSrc ts;
    ts.Ah = Ah + (size_t)m0 * K;
    ts.Al = Al + (size_t)m0 * K;
    ts.Bh = Bh + (size_t)n0 * K;
    ts.Bl = Bl + (size_t)n0 * K;
    ts.K = K; ts.tid = tid;

    const int NK = K / BK;

    load_stage(sb + 0 * STAGE_BYTES, ts, 0);
    load_stage(sb + 1 * STAGE_BYTES, ts, 1);

    float acc[32][4] = {};   // [mt*8+nt][4], warp tile 64x64

    // ldmatrix per-lane base: row (lane&15), col-half (lane>>4)*8
    const uint32_t frag_off = (uint32_t)((lane & 15) * STR_H + (lane >> 4) * 8) * 2;
    const uint32_t a_warp = (uint32_t)(wm * 64) * ROW_B;
    const uint32_t b_warp = (uint32_t)(wn * 64) * ROW_B;

#pragma unroll 1
    for (int kc = 0; kc < NK; kc++) {
        if (kc + 2 < NK) {
            load_stage(sb + ((kc + 2) % NSTAGE) * STAGE_BYTES, ts, kc + 2);
            cp_wait<2>();
        } else {
            cp_wait<0>();
        }
        __syncthreads();
        const uint32_t so = sb + (kc % NSTAGE) * STAGE_BYTES;
#pragma unroll
        for (int kk = 0; kk < 2; kk++) {        // two k16 steps per BK=32 chunk
            const uint32_t ko = (uint32_t)(kk * 16 * 2);
            uint32_t ah[4][4], al[4][4], bh[4][4], bl[4][4];
#pragma unroll
            for (int mt = 0; mt < 4; mt++) {
                const uint32_t ao = a_warp + (uint32_t)(mt * 16) * ROW_B + ko + frag_off;
                ldsm4(ah[mt], so + S_AH + ao);
                ldsm4(al[mt], so + S_AL + ao);
            }
#pragma unroll
            for (int t = 0; t < 4; t++) {
                const uint32_t bo = b_warp + (uint32_t)(t * 16) * ROW_B + ko + frag_off;
                ldsm4(bh[t], so + S_BH + bo);
                ldsm4(bl[t], so + S_BL + bo);
            }
#pragma unroll
            for (int mt = 0; mt < 4; mt++)
#pragma unroll
                for (int nt = 0; nt < 8; nt++) {
                    const int t = nt >> 1, od = nt & 1;
                    float (&c)[4] = acc[mt * 8 + nt];
                    mma16816(c, ah[mt][0], ah[mt][1], ah[mt][2], ah[mt][3],
                             bh[t][od], bh[t][od + 2]);
                    mma16816(c, ah[mt][0], ah[mt][1], ah[mt][2], ah[mt][3],
                             bl[t][od], bl[t][od + 2]);
                    mma16816(c, al[mt][0], al[mt][1], al[mt][2], al[mt][3],
                             bh[t][od], bh[t][od + 2]);
                }
        }
        __syncthreads();
    }

    // -------- epilogue: bias (+ReLU + hi/lo resplit) straight from registers
    const int er = lane >> 2, ec = (lane & 3) * 2;
#pragma unroll
    for (int mt = 0; mt < 4; mt++) {
#pragma unroll
        for (int nt = 0; nt < 8; nt++) {
            const int col = n0 + wn * 64 + nt * 8 + ec;
            const int r0 = m0 + wm * 64 + mt * 16 + er;
            const float2 bv = *reinterpret_cast<const float2*>(bias + col);
            float v0 = acc[mt * 8 + nt][0] + bv.x;
            float v1 = acc[mt * 8 + nt][1] + bv.y;
            float v2 = acc[mt * 8 + nt][2] + bv.x;
            float v3 = acc[mt * 8 + nt][3] + bv.y;
            if (LAST) {
                *reinterpret_cast<float2*>(Cf + (size_t)r0 * Ntot + col)       = make_float2(v0, v1);
                *reinterpret_cast<float2*>(Cf + (size_t)(r0 + 8) * Ntot + col) = make_float2(v2, v3);
            } else {
                v0 = fmaxf(v0, 0.f); v1 = fmaxf(v1, 0.f);
                v2 = fmaxf(v2, 0.f); v3 = fmaxf(v3, 0.f);
                float h0 = __bfloat162float(__float2bfloat16(v0));
                float h1 = __bfloat162float(__float2bfloat16(v1));
                float h2 = __bfloat162float(__float2bfloat16(v2));
                float h3 = __bfloat162float(__float2bfloat16(v3));
                *reinterpret_cast<uint32_t*>(Ch + (size_t)r0 * Ntot + col)       = pack_bf16(h0, h1);
                *reinterpret_cast<uint32_t*>(Ch + (size_t)(r0 + 8) * Ntot + col) = pack_bf16(h2, h3);
                *reinterpret_cast<uint32_t*>(Cl + (size_t)r0 * Ntot + col)       = pack_bf16(v0 - h0, v1 - h1);
                *reinterpret_cast<uint32_t*>(Cl + (size_t)(r0 + 8) * Ntot + col) = pack_bf16(v2 - h2, v3 - h3);
            }
        }
    }
}

// ---------------- prep kernels -------------------
__global__ void __launch_bounds__(256) split_kernel(const float* __restrict__ x,
                                                    __nv_bfloat16* __restrict__ hi,
                                                    __nv_bfloat16* __restrict__ lo, int n) {
    int i = blockIdx.x * 256 + threadIdx.x;
    if (i < n) {
        float v = x[i];
        __nv_bfloat16 h = __float2bfloat16(v);
        hi[i] = h;
        lo[i] = __float2bfloat16(v - __bfloat162float(h));
    }
}

// W [din][dout] fp32 row-major -> Wt hi/lo [dout][din] bf16 row-major
__global__ void __launch_bounds__(256) transpose_split_kernel(
    const float* __restrict__ W, __nv_bfloat16* __restrict__ thi,
    __nv_bfloat16* __restrict__ tlo, int din, int dout) {
    __shared__ float t[32][33];
    const int tx = threadIdx.x, ty = threadIdx.y;
    const int n0 = blockIdx.x * 32, k0 = blockIdx.y * 32;
#pragma unroll
    for (int i = 0; i < 4; i++)
        t[ty + i * 8][tx] = W[(size_t)(k0 + ty + i * 8) * dout + n0 + tx];
    __syncthreads();
#pragma unroll
    for (int i = 0; i < 4; i++) {
        float v = t[tx][ty + i * 8];
        __nv_bfloat16 h = __float2bfloat16(v);
        size_t o = (size_t)(n0 + ty + i * 8) * din + k0 + tx;
        thi[o] = h;
        tlo[o] = __float2bfloat16(v - __bfloat162float(h));
    }
}

// ---------------- bilinear -----------------------
// out[b][a] = sum_f ob[b][a*512+f] * dl[b][f*32+a]
__global__ void __launch_bounds__(256) bilinear_kernel(const float* __restrict__ ob,
                                                       const float* __restrict__ dl,
                                                       float* __restrict__ out) {
    __shared__ float s_dl[64 * 33];
    const int b = blockIdx.x;
    const int tid = threadIdx.x, w = tid >> 5, lane = tid & 31;
    const float* obr = ob + (size_t)b * OUTD;
    const float* dlr = dl + (size_t)b * OUTD;
    float acc[4] = {0.f, 0.f, 0.f, 0.f};
#pragma unroll 1
    for (int f0 = 0; f0 < FDIM; f0 += 64) {
#pragma unroll
        for (int i = 0; i < 8; i++) {
            int t = tid + i * 256;
            s_dl[(t >> 5) * 33 + (t & 31)] = dlr[f0 * ADIM + t];
        }
        __syncthreads();
#pragma unroll
        for (int ai = 0; ai < 4; ai++) {
            const int a = w * 4 + ai;
            const float* po = obr + a * FDIM + f0;
#pragma unroll
            for (int h = 0; h < 2; h++) {
                int ff = h * 32 + lane;
                acc[ai] += po[ff] * s_dl[ff * 33 + a];
            }
        }
        __syncthreads();
    }
#pragma unroll
    for (int ai = 0; ai < 4; ai++) {
        float v = acc[ai];
#pragma unroll
        for (int off = 16; off; off >>= 1) v += __shfl_xor_sync(0xffffffffu, v, off);
        if (lane == 0) out[b * ADIM + w * 4 + ai] = v;
    }
}

// ---------------- host launcher -------------------
static const size_t LOFF[4] = {0, 524288, 4718592, 8912896};
static const int LDIN[4]  = {OBSD, HID, HID, HID};
static const int LDOUT[4] = {HID, HID, HID, OUTD};

extern "C" void kernel_launch(void* const* d_in, const int* in_sizes, int n_in,
                              void* d_out, int out_size) {
    (void)in_sizes; (void)n_in; (void)out_size;
    const float* obs = (const float*)d_in[0];
    const float* del = (const float*)d_in[1];
    const float* W[2][4];
    const float* Bv[2][4];
    for (int l = 0; l < 4; l++) {
        W[0][l]  = (const float*)d_in[2 + l * 4 + 0];
        Bv[0][l] = (const float*)d_in[2 + l * 4 + 1];
        W[1][l]  = (const float*)d_in[2 + l * 4 + 2];
        Bv[1][l] = (const float*)d_in[2 + l * 4 + 3];
    }

    __nv_bfloat16 *wth, *wtl, *ahb, *alb;
    float* tob;
    cudaGetSymbolAddress((void**)&wth, g_wt_hi);
    cudaGetSymbolAddress((void**)&wtl, g_wt_lo);
    cudaGetSymbolAddress((void**)&ahb, g_act_hi);
    cudaGetSymbolAddress((void**)&alb, g_act_lo);
    cudaGetSymbolAddress((void**)&tob, g_tout);
    __nv_bfloat16* AH[2] = {ahb, ahb + (size_t)BATCH * HID};
    __nv_bfloat16* AL[2] = {alb, alb + (size_t)BATCH * HID};
    float* TO[2] = {tob, tob + (size_t)BATCH * OUTD};

    cudaFuncSetAttribute(gemm_kernel<false>, cudaFuncAttributeMaxDynamicSharedMemorySize, GEMM_SMEM);
    cudaFuncSetAttribute(gemm_kernel<true>,  cudaFuncAttributeMaxDynamicSharedMemorySize, GEMM_SMEM);

    // Launch order chosen so ncu (-s 5 -c 1) profiles launch #6 = L1 GEMM.
    for (int t = 0; t < 2; t++) {
        const float* x = (t == 0) ? obs : del;
        const __nv_bfloat16* wh = wth + (size_t)t * TRUNK_W;
        const __nv_bfloat16* wl = wtl + (size_t)t * TRUNK_W;
        __nv_bfloat16* wth_t = wth + (size_t)t * TRUNK_W;
        __nv_bfloat16* wtl_t = wtl + (size_t)t * TRUNK_W;

        auto transpose = [&](int l) {
            dim3 g(LDOUT[l] / 32, LDIN[l] / 32), bl(32, 8);
            transpose_split_kernel<<<g, bl>>>(W[t][l], wth_t + LOFF[l], wtl_t + LOFF[l],
                                              LDIN[l], LDOUT[l]);
        };

        split_kernel<<<(BATCH * OBSD) / 256, 256>>>(x, AH[0], AL[0], BATCH * OBSD);  // 1
        transpose(0);                                                                 // 2
        gemm_kernel<false><<<dim3(32, HID / BN), 256, GEMM_SMEM>>>(                   // 3
            AH[0], AL[0], wh + LOFF[0], wl + LOFF[0], Bv[t][0],
            AH[1], AL[1], nullptr, OBSD, HID);
        transpose(1);                                                                 // 4
        transpose(2);                                                                 // 5
        gemm_kernel<false><<<dim3(32, HID / BN), 256, GEMM_SMEM>>>(                   // 6 (profiled)
            AH[1], AL[1], wh + LOFF[1], wl + LOFF[1], Bv[t][1],
            AH[0], AL[0], nullptr, HID, HID);
        transpose(3);                                                                 // 7
        gemm_kernel<false><<<dim3(32, HID / BN), 256, GEMM_SMEM>>>(                   // 8
            AH[0], AL[0], wh + LOFF[2], wl + LOFF[2], Bv[t][2],
            AH[1], AL[1], nullptr, HID, HID);
        gemm_kernel<true><<<dim3(32, OUTD / BN), 256, GEMM_SMEM>>>(                   // 9
            AH[1], AL[1], wh + LOFF[3], wl + LOFF[3], Bv[t][3],
            nullptr, nullptr, TO[t], HID, OUTD);
    }

    bilinear_kernel<<<BATCH, 256>>>(TO[0], TO[1], (float*)d_out);
}

// round 7
// speedup vs baseline: 1.0766x; 1.0078x over previous
#include <cuda_runtime.h>
#include <cuda_bf16.h>
#include <stdint.h>

// ---------------- problem sizes ----------------
#define BATCH 4096
#define OBSD  256
#define HID   2048
#define OUTD  16384   // FEAT*ACT
#define ADIM  32
#define FDIM  512

// ---------------- scratch (device globals) ----------
#define TRUNK_W 42467328
__device__ __align__(1024) __nv_bfloat16 g_wt_hi[2 * TRUNK_W];
__device__ __align__(1024) __nv_bfloat16 g_wt_lo[2 * TRUNK_W];
__device__ __align__(1024) __nv_bfloat16 g_act_hi[2][BATCH * HID];
__device__ __align__(1024) __nv_bfloat16 g_act_lo[2][BATCH * HID];
__device__ __align__(1024) float         g_tout[2][BATCH * OUTD];

// ---------------- helpers ----------------
static __device__ __forceinline__ uint32_t smem_u32(const void* p) {
    uint32_t a;
    asm volatile("{ .reg .u64 t; cvta.to.shared.u64 t, %1; cvt.u32.u64 %0, t; }"
                 : "=r"(a) : "l"(p));
    return a;
}
static __device__ __forceinline__ void cp16(uint32_t dst, const void* src) {
    asm volatile("cp.async.cg.shared.global [%0], [%1], 16;" :: "r"(dst), "l"(src));
}
static __device__ __forceinline__ void cp_commit() { asm volatile("cp.async.commit_group;"); }
template <int N> static __device__ __forceinline__ void cp_wait() {
    asm volatile("cp.async.wait_group %0;" :: "n"(N) : "memory");
}
static __device__ __forceinline__ void ldsm4(uint32_t (&d)[4], uint32_t addr) {
    asm volatile("ldmatrix.sync.aligned.m8n8.x4.shared.b16 {%0,%1,%2,%3}, [%4];"
                 : "=r"(d[0]), "=r"(d[1]), "=r"(d[2]), "=r"(d[3]) : "r"(addr));
}
static __device__ __forceinline__ void mma16816(float (&c)[4], const uint32_t a0,
                                                const uint32_t a1, const uint32_t a2,
                                                const uint32_t a3, const uint32_t b0,
                                                const uint32_t b1) {
    asm volatile("mma.sync.aligned.m16n8k16.row.col.f32.bf16.bf16.f32 "
                 "{%0,%1,%2,%3}, {%4,%5,%6,%7}, {%8,%9}, {%0,%1,%2,%3};"
                 : "+f"(c[0]), "+f"(c[1]), "+f"(c[2]), "+f"(c[3])
                 : "r"(a0), "r"(a1), "r"(a2), "r"(a3), "r"(b0), "r"(b1));
}
static __device__ __forceinline__ uint32_t pack_bf16(float x, float y) {
    uint32_t r;
    asm("cvt.rn.bf16x2.f32 %0, %1, %2;" : "=r"(r) : "f"(y), "f"(x));
    return r;
}

// ---------------- GEMM (mma.sync, hi/lo 3-pass) -------------------
// C[M, Ntot] = A[M,K] @ B^T (+bias; ReLU+resplit unless LAST)
// Block tile 128x256x32, 8 warps in 2x4 grid, warp tile 64x64.
// Inner loop: 3 sequential pass-sweeps over all 32 accumulators so
// same-accumulator MMAs are ~32 issues apart (RAW chains hidden).
#define BM 128
#define BN 256
#define BK 32
#define STR_H 40                        // halfs per smem row (32 data + 8 pad)
#define ROW_B (STR_H * 2)               // 80 bytes per row
#define A_BYTES (BM * ROW_B)            // 10240
#define B_BYTES (BN * ROW_B)            // 20480
#define S_AH 0
#define S_AL A_BYTES
#define S_BH (2 * A_BYTES)
#define S_BL (2 * A_BYTES + B_BYTES)
#define STAGE_BYTES (2 * A_BYTES + 2 * B_BYTES)   // 61440
#define NSTAGE 3
#define GEMM_SMEM (NSTAGE * STAGE_BYTES)          // 184320

struct TileSrc {
    const __nv_bfloat16 *Ah, *Al, *Bh, *Bl;
    int K, tid;
};

static __device__ __forceinline__ void load_stage(uint32_t so, const TileSrc& ts, int kc) {
    const int k0 = kc * BK;
#pragma unroll
    for (int i = 0; i < 2; i++) {
        const int idx = ts.tid + i * 256;
        const int r = idx >> 2, q = idx & 3;
        const uint32_t o = (uint32_t)(r * ROW_B + q * 16);
        const size_t g = (size_t)r * ts.K + k0 + q * 8;
        cp16(so + S_AH + o, ts.Ah + g);
        cp16(so + S_AL + o, ts.Al + g);
    }
#pragma unroll
    for (int i = 0; i < 4; i++) {
        const int idx = ts.tid + i * 256;
        const int r = idx >> 2, q = idx & 3;
        const uint32_t o = (uint32_t)(r * ROW_B + q * 16);
        const size_t g = (size_t)r * ts.K + k0 + q * 8;
        cp16(so + S_BH + o, ts.Bh + g);
        cp16(so + S_BL + o, ts.Bl + g);
    }
    cp_commit();
}

template <bool LAST>
__global__ void __launch_bounds__(256, 1)
gemm_kernel(const __nv_bfloat16* __restrict__ Ah, const __nv_bfloat16* __restrict__ Al,
            const __nv_bfloat16* __restrict__ Bh, const __nv_bfloat16* __restrict__ Bl,
            const float* __restrict__ bias,
            __nv_bfloat16* __restrict__ Ch, __nv_bfloat16* __restrict__ Cl,
            float* __restrict__ Cf,
            int K, int Ntot)
{
    extern __shared__ char dsm[];
    const uint32_t sb = smem_u32(dsm);
    const int tid = threadIdx.x, wid = tid >> 5, lane = tid & 31;
    const int wm = wid >> 2, wn = wid & 3;          // 2 x 4 warp grid
    const int m0 = blockIdx.x * BM, n0 = blockIdx.y * BN;

    TileSrc ts;
    ts.Ah = Ah + (size_t)m0 * K;
    ts.Al = Al + (size_t)m0 * K;
    ts.Bh = Bh + (size_t)n0 * K;
    ts.Bl = Bl + (size_t)n0 * K;
    ts.K = K; ts.tid = tid;

    const int NK = K / BK;

    load_stage(sb + 0 * STAGE_BYTES, ts, 0);
    load_stage(sb + 1 * STAGE_BYTES, ts, 1);

    float acc[32][4] = {};   // [mt*8+nt][4], warp tile 64x64

    const uint32_t frag_off = (uint32_t)((lane & 15) * STR_H + (lane >> 4) * 8) * 2;
    const uint32_t a_warp = (uint32_t)(wm * 64) * ROW_B;
    const uint32_t b_warp = (uint32_t)(wn * 64) * ROW_B;

#pragma unroll 1
    for (int kc = 0; kc < NK; kc++) {
        if (kc + 2 < NK) {
            load_stage(sb + ((kc + 2) % NSTAGE) * STAGE_BYTES, ts, kc + 2);
            cp_wait<2>();
        } else {
            cp_wait<0>();
        }
        __syncthreads();
        const uint32_t so = sb + (kc % NSTAGE) * STAGE_BYTES;
#pragma unroll
        for (int kk = 0; kk < 2; kk++) {        // two k16 steps per BK=32 chunk
            const uint32_t ko = (uint32_t)(kk * 16 * 2);
            uint32_t ah[4][4], al[4][4], bh[4][4], bl[4][4];
            // loads needed by pass 1 first
#pragma unroll
            for (int mt = 0; mt < 4; mt++) {
                const uint32_t ao = a_warp + (uint32_t)(mt * 16) * ROW_B + ko + frag_off;
                ldsm4(ah[mt], so + S_AH + ao);
            }
#pragma unroll
            for (int t = 0; t < 4; t++) {
                const uint32_t bo = b_warp + (uint32_t)(t * 16) * ROW_B + ko + frag_off;
                ldsm4(bh[t], so + S_BH + bo);
            }
            // pass 1: Ah * Bh   (32 independent accumulators)
#pragma unroll
            for (int mt = 0; mt < 4; mt++)
#pragma unroll
                for (int nt = 0; nt < 8; nt++) {
                    const int t = nt >> 1, od = nt & 1;
                    mma16816(acc[mt * 8 + nt], ah[mt][0], ah[mt][1], ah[mt][2], ah[mt][3],
                             bh[t][od], bh[t][od + 2]);
                }
            // loads for passes 2/3 (latency hidden behind pass 1)
#pragma unroll
            for (int t = 0; t < 4; t++) {
                const uint32_t bo = b_warp + (uint32_t)(t * 16) * ROW_B + ko + frag_off;
                ldsm4(bl[t], so + S_BL + bo);
            }
#pragma unroll
            for (int mt = 0; mt < 4; mt++) {
                const uint32_t ao = a_warp + (uint32_t)(mt * 16) * ROW_B + ko + frag_off;
                ldsm4(al[mt], so + S_AL + ao);
            }
            // pass 2: Ah * Bl
#pragma unroll
            for (int mt = 0; mt < 4; mt++)
#pragma unroll
                for (int nt = 0; nt < 8; nt++) {
                    const int t = nt >> 1, od = nt & 1;
                    mma16816(acc[mt * 8 + nt], ah[mt][0], ah[mt][1], ah[mt][2], ah[mt][3],
                             bl[t][od], bl[t][od + 2]);
                }
            // pass 3: Al * Bh
#pragma unroll
            for (int mt = 0; mt < 4; mt++)
#pragma unroll
                for (int nt = 0; nt < 8; nt++) {
                    const int t = nt >> 1, od = nt & 1;
                    mma16816(acc[mt * 8 + nt], al[mt][0], al[mt][1], al[mt][2], al[mt][3],
                             bh[t][od], bh[t][od + 2]);
                }
        }
        __syncthreads();
    }

    // -------- epilogue: bias (+ReLU + hi/lo resplit) straight from registers
    const int er = lane >> 2, ec = (lane & 3) * 2;
#pragma unroll
    for (int mt = 0; mt < 4; mt++) {
#pragma unroll
        for (int nt = 0; nt < 8; nt++) {
            const int col = n0 + wn * 64 + nt * 8 + ec;
            const int r0 = m0 + wm * 64 + mt * 16 + er;
            const float2 bv = *reinterpret_cast<const float2*>(bias + col);
            float v0 = acc[mt * 8 + nt][0] + bv.x;
            float v1 = acc[mt * 8 + nt][1] + bv.y;
            float v2 = acc[mt * 8 + nt][2] + bv.x;
            float v3 = acc[mt * 8 + nt][3] + bv.y;
            if (LAST) {
                *reinterpret_cast<float2*>(Cf + (size_t)r0 * Ntot + col)       = make_float2(v0, v1);
                *reinterpret_cast<float2*>(Cf + (size_t)(r0 + 8) * Ntot + col) = make_float2(v2, v3);
            } else {
                v0 = fmaxf(v0, 0.f); v1 = fmaxf(v1, 0.f);
                v2 = fmaxf(v2, 0.f); v3 = fmaxf(v3, 0.f);
                float h0 = __bfloat162float(__float2bfloat16(v0));
                float h1 = __bfloat162float(__float2bfloat16(v1));
                float h2 = __bfloat162float(__float2bfloat16(v2));
                float h3 = __bfloat162float(__float2bfloat16(v3));
                *reinterpret_cast<uint32_t*>(Ch + (size_t)r0 * Ntot + col)       = pack_bf16(h0, h1);
                *reinterpret_cast<uint32_t*>(Ch + (size_t)(r0 + 8) * Ntot + col) = pack_bf16(h2, h3);
                *reinterpret_cast<uint32_t*>(Cl + (size_t)r0 * Ntot + col)       = pack_bf16(v0 - h0, v1 - h1);
                *reinterpret_cast<uint32_t*>(Cl + (size_t)(r0 + 8) * Ntot + col) = pack_bf16(v2 - h2, v3 - h3);
            }
        }
    }
}

// ---------------- prep kernels -------------------
__global__ void __launch_bounds__(256) split_kernel(const float* __restrict__ x,
                                                    __nv_bfloat16* __restrict__ hi,
                                                    __nv_bfloat16* __restrict__ lo, int n) {
    int i = blockIdx.x * 256 + threadIdx.x;
    if (i < n) {
        float v = x[i];
        __nv_bfloat16 h = __float2bfloat16(v);
        hi[i] = h;
        lo[i] = __float2bfloat16(v - __bfloat162float(h));
    }
}

// W [din][dout] fp32 row-major -> Wt hi/lo [dout][din] bf16 row-major
__global__ void __launch_bounds__(256) transpose_split_kernel(
    const float* __restrict__ W, __nv_bfloat16* __restrict__ thi,
    __nv_bfloat16* __restrict__ tlo, int din, int dout) {
    __shared__ float t[32][33];
    const int tx = threadIdx.x, ty = threadIdx.y;
    const int n0 = blockIdx.x * 32, k0 = blockIdx.y * 32;
#pragma unroll
    for (int i = 0; i < 4; i++)
        t[ty + i * 8][tx] = W[(size_t)(k0 + ty + i * 8) * dout + n0 + tx];
    __syncthreads();
#pragma unroll
    for (int i = 0; i < 4; i++) {
        float v = t[tx][ty + i * 8];
        __nv_bfloat16 h = __float2bfloat16(v);
        size_t o = (size_t)(n0 + ty + i * 8) * din + k0 + tx;
        thi[o] = h;
        tlo[o] = __float2bfloat16(v - __bfloat162float(h));
    }
}

// ---------------- bilinear -----------------------
// out[b][a] = sum_f ob[b][a*512+f] * dl[b][f*32+a]
__global__ void __launch_bounds__(256) bilinear_kernel(const float* __restrict__ ob,
                                                       const float* __restrict__ dl,
                                                       float* __restrict__ out) {
    __shared__ float s_dl[64 * 33];
    const int b = blockIdx.x;
    const int tid = threadIdx.x, w = tid >> 5, lane = tid & 31;
    const float* obr = ob + (size_t)b * OUTD;
    const float* dlr = dl + (size_t)b * OUTD;
    float acc[4] = {0.f, 0.f, 0.f, 0.f};
#pragma unroll 1
    for (int f0 = 0; f0 < FDIM; f0 += 64) {
#pragma unroll
        for (int i = 0; i < 8; i++) {
            int t = tid + i * 256;
            s_dl[(t >> 5) * 33 + (t & 31)] = dlr[f0 * ADIM + t];
        }
        __syncthreads();
#pragma unroll
        for (int ai = 0; ai < 4; ai++) {
            const int a = w * 4 + ai;
            const float* po = obr + a * FDIM + f0;
#pragma unroll
            for (int h = 0; h < 2; h++) {
                int ff = h * 32 + lane;
                acc[ai] += po[ff] * s_dl[ff * 33 + a];
            }
        }
        __syncthreads();
    }
#pragma unroll
    for (int ai = 0; ai < 4; ai++) {
        float v = acc[ai];
#pragma unroll
        for (int off = 16; off; off >>= 1) v += __shfl_xor_sync(0xffffffffu, v, off);
        if (lane == 0) out[b * ADIM + w * 4 + ai] = v;
    }
}

// ---------------- host launcher -------------------
static const size_t LOFF[4] = {0, 524288, 4718592, 8912896};
static const int LDIN[4]  = {OBSD, HID, HID, HID};
static const int LDOUT[4] = {HID, HID, HID, OUTD};

extern "C" void kernel_launch(void* const* d_in, const int* in_sizes, int n_in,
                              void* d_out, int out_size) {
    (void)in_sizes; (void)n_in; (void)out_size;
    const float* obs = (const float*)d_in[0];
    const float* del = (const float*)d_in[1];
    const float* W[2][4];
    const float* Bv[2][4];
    for (int l = 0; l < 4; l++) {
        W[0][l]  = (const float*)d_in[2 + l * 4 + 0];
        Bv[0][l] = (const float*)d_in[2 + l * 4 + 1];
        W[1][l]  = (const float*)d_in[2 + l * 4 + 2];
        Bv[1][l] = (const float*)d_in[2 + l * 4 + 3];
    }

    __nv_bfloat16 *wth, *wtl, *ahb, *alb;
    float* tob;
    cudaGetSymbolAddress((void**)&wth, g_wt_hi);
    cudaGetSymbolAddress((void**)&wtl, g_wt_lo);
    cudaGetSymbolAddress((void**)&ahb, g_act_hi);
    cudaGetSymbolAddress((void**)&alb, g_act_lo);
    cudaGetSymbolAddress((void**)&tob, g_tout);
    __nv_bfloat16* AH[2] = {ahb, ahb + (size_t)BATCH * HID};
    __nv_bfloat16* AL[2] = {alb, alb + (size_t)BATCH * HID};
    float* TO[2] = {tob, tob + (size_t)BATCH * OUTD};

    cudaFuncSetAttribute(gemm_kernel<false>, cudaFuncAttributeMaxDynamicSharedMemorySize, GEMM_SMEM);
    cudaFuncSetAttribute(gemm_kernel<true>,  cudaFuncAttributeMaxDynamicSharedMemorySize, GEMM_SMEM);

    for (int t = 0; t < 2; t++) {
        const float* x = (t == 0) ? obs : del;
        const __nv_bfloat16* wh = wth + (size_t)t * TRUNK_W;
        const __nv_bfloat16* wl = wtl + (size_t)t * TRUNK_W;
        __nv_bfloat16* wth_t = wth + (size_t)t * TRUNK_W;
        __nv_bfloat16* wtl_t = wtl + (size_t)t * TRUNK_W;

        auto transpose = [&](int l) {
            dim3 g(LDOUT[l] / 32, LDIN[l] / 32), bl(32, 8);
            transpose_split_kernel<<<g, bl>>>(W[t][l], wth_t + LOFF[l], wtl_t + LOFF[l],
                                              LDIN[l], LDOUT[l]);
        };

        split_kernel<<<(BATCH * OBSD) / 256, 256>>>(x, AH[0], AL[0], BATCH * OBSD);
        transpose(0);
        gemm_kernel<false><<<dim3(32, HID / BN), 256, GEMM_SMEM>>>(
            AH[0], AL[0], wh + LOFF[0], wl + LOFF[0], Bv[t][0],
            AH[1], AL[1], nullptr, OBSD, HID);
        transpose(1);
        transpose(2);
        gemm_kernel<false><<<dim3(32, HID / BN), 256, GEMM_SMEM>>>(
            AH[1], AL[1], wh + LOFF[1], wl + LOFF[1], Bv[t][1],
            AH[0], AL[0], nullptr, HID, HID);
        transpose(3);
        gemm_kernel<false><<<dim3(32, HID / BN), 256, GEMM_SMEM>>>(
            AH[0], AL[0], wh + LOFF[2], wl + LOFF[2], Bv[t][2],
            AH[1], AL[1], nullptr, HID, HID);
        gemm_kernel<true><<<dim3(32, OUTD / BN), 256, GEMM_SMEM>>>(
            AH[1], AL[1], wh + LOFF[3], wl + LOFF[3], Bv[t][3],
            nullptr, nullptr, TO[t], HID, OUTD);
    }

    bilinear_kernel<<<BATCH, 256>>>(TO[0], TO[1], (float*)d_out);
}

// round 12
// speedup vs baseline: 1.1492x; 1.0674x over previous
#include <cuda_runtime.h>
#include <cuda_bf16.h>
#include <stdint.h>

// ---------------- problem sizes ----------------
#define BATCH 4096
#define OBSD  256
#define HID   2048
#define OUTD  16384   // FEAT*ACT
#define ADIM  32
#define FDIM  512

// ---------------- scratch (device globals) ----------
#define TRUNK_W 42467328
__device__ __align__(1024) __nv_bfloat16 g_wt_hi[2 * TRUNK_W];
__device__ __align__(1024) __nv_bfloat16 g_wt_lo[2 * TRUNK_W];
__device__ __align__(1024) __nv_bfloat16 g_act_hi[4][BATCH * HID];
__device__ __align__(1024) __nv_bfloat16 g_act_lo[4][BATCH * HID];
__device__ __align__(1024) float         g_tout[2][BATCH * OUTD];

// ---------------- helpers ----------------
static __device__ __forceinline__ uint32_t smem_u32(const void* p) {
    uint32_t a;
    asm volatile("{ .reg .u64 t; cvta.to.shared.u64 t, %1; cvt.u32.u64 %0, t; }"
                 : "=r"(a) : "l"(p));
    return a;
}
static __device__ __forceinline__ void cp16(uint32_t dst, const void* src) {
    asm volatile("cp.async.cg.shared.global [%0], [%1], 16;" :: "r"(dst), "l"(src));
}
static __device__ __forceinline__ void cp_commit() { asm volatile("cp.async.commit_group;"); }
template <int N> static __device__ __forceinline__ void cp_wait() {
    asm volatile("cp.async.wait_group %0;" :: "n"(N) : "memory");
}
static __device__ __forceinline__ void ldsm4(uint32_t (&d)[4], uint32_t addr) {
    asm volatile("ldmatrix.sync.aligned.m8n8.x4.shared.b16 {%0,%1,%2,%3}, [%4];"
                 : "=r"(d[0]), "=r"(d[1]), "=r"(d[2]), "=r"(d[3]) : "r"(addr));
}
static __device__ __forceinline__ void mma16816(float (&c)[4], const uint32_t a0,
                                                const uint32_t a1, const uint32_t a2,
                                                const uint32_t a3, const uint32_t b0,
                                                const uint32_t b1) {
    asm volatile("mma.sync.aligned.m16n8k16.row.col.f32.bf16.bf16.f32 "
                 "{%0,%1,%2,%3}, {%4,%5,%6,%7}, {%8,%9}, {%0,%1,%2,%3};"
                 : "+f"(c[0]), "+f"(c[1]), "+f"(c[2]), "+f"(c[3])
                 : "r"(a0), "r"(a1), "r"(a2), "r"(a3), "r"(b0), "r"(b1));
}
static __device__ __forceinline__ uint32_t pack_bf16(float x, float y) {
    uint32_t r;
    asm("cvt.rn.bf16x2.f32 %0, %1, %2;" : "=r"(r) : "f"(y), "f"(x));
    return r;
}

// ---------------- GEMM (mma.sync, hi/lo 3-pass) -------------------
// C[M, Ntot] = A[M,K] @ B^T (+bias; ReLU+resplit unless LAST)
// Block tile 128x128x32, 8 warps (2x4), warp tile 64x32.
// 2-stage cp.async pipeline, 2 CTAs/SM for cross-CTA latency hiding.
#define BM 128
#define BN 128
#define BK 32
#define STR_H 40                        // halfs per smem row (32 data + 8 pad)
#define ROW_B (STR_H * 2)               // 80 bytes per row
#define ARR_B (BM * ROW_B)              // 10240 bytes per array
#define S_AH 0
#define S_AL ARR_B
#define S_BH (2 * ARR_B)
#define S_BL (3 * ARR_B)
#define STAGE_BYTES (4 * ARR_B)         // 40960
#define GEMM_SMEM (2 * STAGE_BYTES)     // 81920 -> 2 CTAs/SM

struct TileSrc {
    const __nv_bfloat16 *Ah, *Al, *Bh, *Bl;
    int K, tid;
};

static __device__ __forceinline__ void load_stage(uint32_t so, const TileSrc& ts, int kc) {
    const int k0 = kc * BK;
#pragma unroll
    for (int i = 0; i < 2; i++) {
        const int idx = ts.tid + i * 256;      // 0..511
        const int r = idx >> 2, q = idx & 3;
        const uint32_t o = (uint32_t)(r * ROW_B + q * 16);
        const size_t g = (size_t)r * ts.K + k0 + q * 8;
        cp16(so + S_AH + o, ts.Ah + g);
        cp16(so + S_AL + o, ts.Al + g);
        cp16(so + S_BH + o, ts.Bh + g);
        cp16(so + S_BL + o, ts.Bl + g);
    }
    cp_commit();
}

template <bool LAST>
__global__ void __launch_bounds__(256, 2)
gemm_kernel(const __nv_bfloat16* __restrict__ Ah, const __nv_bfloat16* __restrict__ Al,
            const __nv_bfloat16* __restrict__ Bh, const __nv_bfloat16* __restrict__ Bl,
            const float* __restrict__ bias,
            __nv_bfloat16* __restrict__ Ch, __nv_bfloat16* __restrict__ Cl,
            float* __restrict__ Cf,
            int K, int Ntot)
{
    extern __shared__ char dsm[];
    const uint32_t sb = smem_u32(dsm);
    const int tid = threadIdx.x, wid = tid >> 5, lane = tid & 31;
    const int wm = wid >> 2, wn = wid & 3;          // 2 x 4 warp grid
    const int m0 = blockIdx.x * BM, n0 = blockIdx.y * BN;

    TileSrc ts;
    ts.Ah = Ah + (size_t)m0 * K;
    ts.Al = Al + (size_t)m0 * K;
    ts.Bh = Bh + (size_t)n0 * K;
    ts.Bl = Bl + (size_t)n0 * K;
    ts.K = K; ts.tid = tid;

    const int NK = K / BK;

    load_stage(sb + 0 * STAGE_BYTES, ts, 0);
    load_stage(sb + 1 * STAGE_BYTES, ts, 1);

    float acc[16][4] = {};   // [mt*4+nt][4], warp tile 64x32

    const uint32_t frag_off = (uint32_t)((lane & 15) * STR_H + (lane >> 4) * 8) * 2;
    const uint32_t a_warp = (uint32_t)(wm * 64) * ROW_B;
    const uint32_t b_warp = (uint32_t)(wn * 32) * ROW_B;

#pragma unroll 1
    for (int kc = 0; kc < NK; kc++) {
        if (kc + 1 < NK) cp_wait<1>(); else cp_wait<0>();
        __syncthreads();
        const uint32_t so = sb + (kc & 1) * STAGE_BYTES;
#pragma unroll
        for (int kk = 0; kk < 2; kk++) {        // two k16 steps per BK=32 chunk
            const uint32_t ko = (uint32_t)(kk * 16 * 2);
            uint32_t ah[4][4], al[4][4], bh[2][4], bl[2][4];
#pragma unroll
            for (int mt = 0; mt < 4; mt++)
                ldsm4(ah[mt], so + S_AH + a_warp + (uint32_t)(mt * 16) * ROW_B + ko + frag_off);
#pragma unroll
            for (int t = 0; t < 2; t++)
                ldsm4(bh[t], so + S_BH + b_warp + (uint32_t)(t * 16) * ROW_B + ko + frag_off);
            // pass 1: Ah * Bh  (16 independent accumulators)
#pragma unroll
            for (int mt = 0; mt < 4; mt++)
#pragma unroll
                for (int nt = 0; nt < 4; nt++) {
                    const int t = nt >> 1, od = nt & 1;
                    mma16816(acc[mt * 4 + nt], ah[mt][0], ah[mt][1], ah[mt][2], ah[mt][3],
                             bh[t][od], bh[t][od + 2]);
                }
#pragma unroll
            for (int t = 0; t < 2; t++)
                ldsm4(bl[t], so + S_BL + b_warp + (uint32_t)(t * 16) * ROW_B + ko + frag_off);
            // pass 2: Ah * Bl
#pragma unroll
            for (int mt = 0; mt < 4; mt++)
#pragma unroll
                for (int nt = 0; nt < 4; nt++) {
                    const int t = nt >> 1, od = nt & 1;
                    mma16816(acc[mt * 4 + nt], ah[mt][0], ah[mt][1], ah[mt][2], ah[mt][3],
                             bl[t][od], bl[t][od + 2]);
                }
#pragma unroll
            for (int mt = 0; mt < 4; mt++)
                ldsm4(al[mt], so + S_AL + a_warp + (uint32_t)(mt * 16) * ROW_B + ko + frag_off);
            // pass 3: Al * Bh
#pragma unroll
            for (int mt = 0; mt < 4; mt++)
#pragma unroll
                for (int nt = 0; nt < 4; nt++) {
                    const int t = nt >> 1, od = nt & 1;
                    mma16816(acc[mt * 4 + nt], al[mt][0], al[mt][1], al[mt][2], al[mt][3],
                             bh[t][od], bh[t][od + 2]);
                }
        }
        __syncthreads();
        if (kc + 2 < NK) load_stage(so, ts, kc + 2);   // same stage, just retired
    }

    // -------- epilogue: bias (+ReLU + hi/lo resplit) straight from registers
    const int er = lane >> 2, ec = (lane & 3) * 2;
#pragma unroll
    for (int mt = 0; mt < 4; mt++) {
#pragma unroll
        for (int nt = 0; nt < 4; nt++) {
            const int col = n0 + wn * 32 + nt * 8 + ec;
            const int r0 = m0 + wm * 64 + mt * 16 + er;
            const float2 bv = *reinterpret_cast<const float2*>(bias + col);
            float v0 = acc[mt * 4 + nt][0] + bv.x;
            float v1 = acc[mt * 4 + nt][1] + bv.y;
            float v2 = acc[mt * 4 + nt][2] + bv.x;
            float v3 = acc[mt * 4 + nt][3] + bv.y;
            if (LAST) {
                *reinterpret_cast<float2*>(Cf + (size_t)r0 * Ntot + col)       = make_float2(v0, v1);
                *reinterpret_cast<float2*>(Cf + (size_t)(r0 + 8) * Ntot + col) = make_float2(v2, v3);
            } else {
                v0 = fmaxf(v0, 0.f); v1 = fmaxf(v1, 0.f);
                v2 = fmaxf(v2, 0.f); v3 = fmaxf(v3, 0.f);
                float h0 = __bfloat162float(__float2bfloat16(v0));
                float h1 = __bfloat162float(__float2bfloat16(v1));
                float h2 = __bfloat162float(__float2bfloat16(v2));
                float h3 = __bfloat162float(__float2bfloat16(v3));
                *reinterpret_cast<uint32_t*>(Ch + (size_t)r0 * Ntot + col)       = pack_bf16(h0, h1);
                *reinterpret_cast<uint32_t*>(Ch + (size_t)(r0 + 8) * Ntot + col) = pack_bf16(h2, h3);
                *reinterpret_cast<uint32_t*>(Cl + (size_t)r0 * Ntot + col)       = pack_bf16(v0 - h0, v1 - h1);
                *reinterpret_cast<uint32_t*>(Cl + (size_t)(r0 + 8) * Ntot + col) = pack_bf16(v2 - h2, v3 - h3);
            }
        }
    }
}

// ---------------- prep kernels -------------------
__global__ void __launch_bounds__(256) split_kernel(const float* __restrict__ x,
                                                    __nv_bfloat16* __restrict__ hi,
                                                    __nv_bfloat16* __restrict__ lo, int n) {
    int i = blockIdx.x * 256 + threadIdx.x;
    if (i < n) {
        float v = x[i];
        __nv_bfloat16 h = __float2bfloat16(v);
        hi[i] = h;
        lo[i] = __float2bfloat16(v - __bfloat162float(h));
    }
}

// All 8 weight transposes (2 trunks x 4 layers) in ONE launch.
struct PrepArgs {
    const float* W[8];
    __nv_bfloat16* hi[8];
    __nv_bfloat16* lo[8];
    int din[8], dout[8];
    int cum[9];   // block-count prefix sums
};

__global__ void __launch_bounds__(256) prep_weights_kernel(PrepArgs a) {
    __shared__ float t[32][33];
    int bid = blockIdx.x;
    int s = 0;
#pragma unroll
    for (int i = 0; i < 7; i++) s += (bid >= a.cum[i + 1]) ? 1 : 0;
    const int local = bid - a.cum[s];
    const int din = a.din[s], dout = a.dout[s];
    const int nx = dout / 32;
    const int n0 = (local % nx) * 32, k0 = (local / nx) * 32;
    const float* W = a.W[s];
    __nv_bfloat16* thi = a.hi[s];
    __nv_bfloat16* tlo = a.lo[s];

    const int tx = threadIdx.x, ty = threadIdx.y;
#pragma unroll
    for (int i = 0; i < 4; i++)
        t[ty + i * 8][tx] = W[(size_t)(k0 + ty + i * 8) * dout + n0 + tx];
    __syncthreads();
#pragma unroll
    for (int i = 0; i < 4; i++) {
        float v = t[tx][ty + i * 8];
        __nv_bfloat16 h = __float2bfloat16(v);
        size_t o = (size_t)(n0 + ty + i * 8) * din + k0 + tx;
        thi[o] = h;
        tlo[o] = __float2bfloat16(v - __bfloat162float(h));
    }
}

// ---------------- bilinear -----------------------
// out[b][a] = sum_f ob[b][a*512+f] * dl[b][f*32+a]
__global__ void __launch_bounds__(256) bilinear_kernel(const float* __restrict__ ob,
                                                       const float* __restrict__ dl,
                                                       float* __restrict__ out) {
    __shared__ float s_dl[64 * 33];
    const int b = blockIdx.x;
    const int tid = threadIdx.x, w = tid >> 5, lane = tid & 31;
    const float* obr = ob + (size_t)b * OUTD;
    const float* dlr = dl + (size_t)b * OUTD;
    float acc[4] = {0.f, 0.f, 0.f, 0.f};
#pragma unroll 1
    for (int f0 = 0; f0 < FDIM; f0 += 64) {
#pragma unroll
        for (int i = 0; i < 8; i++) {
            int t = tid + i * 256;
            s_dl[(t >> 5) * 33 + (t & 31)] = dlr[f0 * ADIM + t];
        }
        __syncthreads();
#pragma unroll
        for (int ai = 0; ai < 4; ai++) {
            const int a = w * 4 + ai;
            const float* po = obr + a * FDIM + f0;
#pragma unroll
            for (int h = 0; h < 2; h++) {
                int ff = h * 32 + lane;
                acc[ai] += po[ff] * s_dl[ff * 33 + a];
            }
        }
        __syncthreads();
    }
#pragma unroll
    for (int ai = 0; ai < 4; ai++) {
        float v = acc[ai];
#pragma unroll
        for (int off = 16; off; off >>= 1) v += __shfl_xor_sync(0xffffffffu, v, off);
        if (lane == 0) out[b * ADIM + w * 4 + ai] = v;
    }
}

// ---------------- host launcher -------------------
static const size_t LOFF[4] = {0, 524288, 4718592, 8912896};
static const int LDIN[4]  = {OBSD, HID, HID, HID};
static const int LDOUT[4] = {HID, HID, HID, OUTD};

extern "C" void kernel_launch(void* const* d_in, const int* in_sizes, int n_in,
                              void* d_out, int out_size) {
    (void)in_sizes; (void)n_in; (void)out_size;
    const float* obs = (const float*)d_in[0];
    const float* del = (const float*)d_in[1];
    const float* W[2][4];
    const float* Bv[2][4];
    for (int l = 0; l < 4; l++) {
        W[0][l]  = (const float*)d_in[2 + l * 4 + 0];
        Bv[0][l] = (const float*)d_in[2 + l * 4 + 1];
        W[1][l]  = (const float*)d_in[2 + l * 4 + 2];
        Bv[1][l] = (const float*)d_in[2 + l * 4 + 3];
    }

    __nv_bfloat16 *wth, *wtl, *ahb, *alb;
    float* tob;
    cudaGetSymbolAddress((void**)&wth, g_wt_hi);
    cudaGetSymbolAddress((void**)&wtl, g_wt_lo);
    cudaGetSymbolAddress((void**)&ahb, g_act_hi);
    cudaGetSymbolAddress((void**)&alb, g_act_lo);
    cudaGetSymbolAddress((void**)&tob, g_tout);
    __nv_bfloat16* AH[4]; __nv_bfloat16* AL[4];
    for (int i = 0; i < 4; i++) {
        AH[i] = ahb + (size_t)i * BATCH * HID;
        AL[i] = alb + (size_t)i * BATCH * HID;
    }
    float* TO[2] = {tob, tob + (size_t)BATCH * OUTD};

    cudaFuncSetAttribute(gemm_kernel<false>, cudaFuncAttributeMaxDynamicSharedMemorySize, GEMM_SMEM);
    cudaFuncSetAttribute(gemm_kernel<true>,  cudaFuncAttributeMaxDynamicSharedMemorySize, GEMM_SMEM);

    // prep args: slot s = t*4 + l
    PrepArgs pa;
    int cum = 0;
    for (int t = 0; t < 2; t++)
        for (int l = 0; l < 4; l++) {
            int s = t * 4 + l;
            pa.W[s] = W[t][l];
            pa.hi[s] = wth + (size_t)t * TRUNK_W + LOFF[l];
            pa.lo[s] = wtl + (size_t)t * TRUNK_W + LOFF[l];
            pa.din[s] = LDIN[l];
            pa.dout[s] = LDOUT[l];
            pa.cum[s] = cum;
            cum += (LDOUT[l] / 32) * (LDIN[l] / 32);
        }
    pa.cum[8] = cum;

    // launches 1-3: all prep
    split_kernel<<<(BATCH * OBSD) / 256, 256>>>(obs, AH[0], AL[0], BATCH * OBSD);
    split_kernel<<<(BATCH * OBSD) / 256, 256>>>(del, AH[2], AL[2], BATCH * OBSD);
    prep_weights_kernel<<<cum, dim3(32, 8)>>>(pa);

    // launches 4-11: pure GEMM stream (ncu lands here)
    for (int t = 0; t < 2; t++) {
        const __nv_bfloat16* wh = wth + (size_t)t * TRUNK_W;
        const __nv_bfloat16* wl = wtl + (size_t)t * TRUNK_W;
        const int i0 = t * 2, i1 = t * 2 + 1;
        gemm_kernel<false><<<dim3(BATCH / BM, HID / BN), 256, GEMM_SMEM>>>(
            AH[i0], AL[i0], wh + LOFF[0], wl + LOFF[0], Bv[t][0],
            AH[i1], AL[i1], nullptr, OBSD, HID);
        gemm_kernel<false><<<dim3(BATCH / BM, HID / BN), 256, GEMM_SMEM>>>(
            AH[i1], AL[i1], wh + LOFF[1], wl + LOFF[1], Bv[t][1],
            AH[i0], AL[i0], nullptr, HID, HID);
        gemm_kernel<false><<<dim3(BATCH / BM, HID / BN), 256, GEMM_SMEM>>>(
            AH[i0], AL[i0], wh + LOFF[2], wl + LOFF[2], Bv[t][2],
            AH[i1], AL[i1], nullptr, HID, HID);
        gemm_kernel<true><<<dim3(BATCH / BM, OUTD / BN), 256, GEMM_SMEM>>>(
            AH[i1], AL[i1], wh + LOFF[3], wl + LOFF[3], Bv[t][3],
            nullptr, nullptr, TO[t], HID, OUTD);
    }

    bilinear_kernel<<<BATCH, 256>>>(TO[0], TO[1], (float*)d_out);
}